// round 13
// baseline (speedup 1.0000x reference)
#include <cuda_runtime.h>
#include <cuda_fp16.h>
#include <cstdint>

// ---------------------------------------------------------------------------
// Scratch (__device__ globals — no allocations allowed)
// ---------------------------------------------------------------------------
static __device__ float  g_T[16 * 16 * 16 * 16 * 16];   //  4 MB  T[i][j][m][n][s]
static __device__ __half g_Wh[4096 * 4096];             // 32 MB  Wh[n=mno][k=ijk], fp16 x1024
static __device__ __half g_Xh[2048 * 4096];             // 16 MB  X fp16

#define W_SCALE   1024.0f
#define INV_SCALE 0.0009765625f

// ---------------------------------------------------------------------------
// Prep A (merged, independent halves — proven, 12us):
//   blocks [0,256):    stage1  T[i,j,m,n,s] = sum_r first[i,r,m]*middle[j,r,s,n]
//   blocks [256,8448): convx   X float4 -> fp16
// ---------------------------------------------------------------------------
__global__ void mpo_prepA(const float* __restrict__ first,
                          const float* __restrict__ middle,
                          const float* __restrict__ x) {
    __shared__ float F[256];     // first[i][r][m]
    __shared__ float Md[4096];   // middle[j][r][s][n]
    const int t = threadIdx.x;
    if (blockIdx.x >= 256) {
        int id = (blockIdx.x - 256) * 256 + t;      // float4 index
        float4 v = ((const float4*)x)[id];
        __half2 lo = __floats2half2_rn(v.x, v.y);
        __half2 hi = __floats2half2_rn(v.z, v.w);
        uint2 p;
        p.x = *(uint32_t*)&lo;
        p.y = *(uint32_t*)&hi;
        ((uint2*)g_Xh)[id] = p;
        return;
    }
    const int i = blockIdx.x >> 4, j = blockIdx.x & 15;
    F[t] = first[i * 256 + t];
#pragma unroll
    for (int q = 0; q < 16; q++) Md[t + q * 256] = middle[j * 4096 + t + q * 256];
    __syncthreads();
#pragma unroll
    for (int q = 0; q < 16; q++) {
        int z = t + q * 256;                 // z = m*256 + n*16 + s
        int m = z >> 8, n = (z >> 4) & 15, s = z & 15;
        float acc = 0.f;
#pragma unroll
        for (int r = 0; r < 16; r++)
            acc += F[r * 16 + m] * Md[r * 256 + s * 16 + n];
        g_T[(i * 16 + j) * 4096 + z] = acc;
    }
}

// ---------------------------------------------------------------------------
// Stage 2 (o-split x4, proven): block b -> (m=b>>6, n=(b>>2)&15, og=b&3)
// ---------------------------------------------------------------------------
__global__ void mpo_stage2(const float* __restrict__ last) {
    __shared__ float L[4096];    // last[k][s][o]
    const int t = threadIdx.x;
    const int m = blockIdx.x >> 6, n = (blockIdx.x >> 2) & 15, og = blockIdx.x & 3;
#pragma unroll
    for (int q = 0; q < 16; q++) L[t + q * 256] = last[t + q * 256];
    float Ts[16];
    const float* tp = g_T + (size_t)t * 4096 + m * 256 + n * 16;
#pragma unroll
    for (int s = 0; s < 16; s++) Ts[s] = tp[s];
    __syncthreads();
#pragma unroll
    for (int oo = 0; oo < 4; oo++) {
        const int o = og * 4 + oo;
        __half v[16];
#pragma unroll
        for (int k = 0; k < 16; k++) {
            float acc = 0.f;
#pragma unroll
            for (int s = 0; s < 16; s++) acc += Ts[s] * L[k * 256 + s * 16 + o];
            v[k] = __float2half_rn(acc * W_SCALE);
        }
        __half* wp = g_Wh + (size_t)(m * 256 + n * 16 + o) * 4096 + t * 16;
        *(uint4*)(wp)     = *(const uint4*)(v);
        *(uint4*)(wp + 8) = *(const uint4*)(v + 8);
    }
}

// ---------------------------------------------------------------------------
// GEMM: out(2048x4096) = (Xh @ Wh^T) * 2^-10 + bias
// Round-9 proven kernel with ONE change: NSTAGE 4 -> 5 (wait_group 2 -> 3).
// 128 thr, 4 warps (64x64), BK=32, HSTR 40, issue at END of loop body.
// ---------------------------------------------------------------------------
#define HSTR 40
#define TILE_B (128 * HSTR * 2)        // 10240 B per operand tile
#define STG_B  (2 * TILE_B)            // 20480 B per stage
#define NSTAGE 5
#define SMEM_BYTES (NSTAGE * STG_B)    // 102400 B

__device__ __forceinline__ void cpa16(uint32_t saddr, const void* gaddr) {
    asm volatile("cp.async.cg.shared.global [%0], [%1], 16;"
                 :: "r"(saddr), "l"(gaddr));
}

__global__ void __launch_bounds__(128, 2)
mpo_gemm(const float* __restrict__ bias, float* __restrict__ out) {
    extern __shared__ char sm[];
    uint32_t smb;
    asm("{ .reg .u64 t; cvta.to.shared.u64 t, %1; cvt.u32.u64 %0, t; }"
        : "=r"(smb) : "l"(sm));
    const int tid  = threadIdx.x;
    const int lane = tid & 31, wid = tid >> 5;
    const int gid  = lane >> 2, tig = lane & 3;
    const int warpM = wid & 1, warpN = wid >> 1;   // 2M x 2N warps
    const int bM = blockIdx.y << 7;
    const int bN = blockIdx.x << 7;

    float acc[4][8][4];
#pragma unroll
    for (int mt = 0; mt < 4; mt++)
#pragma unroll
        for (int nt = 0; nt < 8; nt++)
#pragma unroll
            for (int q = 0; q < 4; q++) acc[mt][nt][q] = 0.f;

    auto issue = [&](int kt, int stg) {
        const uint32_t so = smb + (uint32_t)stg * STG_B;
        const __half* gA = g_Xh + (size_t)bM * 4096 + kt * 32;
        const __half* gB = g_Wh + (size_t)bN * 4096 + kt * 32;
#pragma unroll
        for (int i = 0; i < 4; i++) {
            int z = tid + i * 128, r = z >> 2, c = z & 3;
            uint32_t off = (uint32_t)(r * HSTR + c * 8) * 2;
            cpa16(so + off, gA + (size_t)r * 4096 + c * 8);
            cpa16(so + TILE_B + off, gB + (size_t)r * 4096 + c * 8);
        }
    };

    issue(0, 0); asm volatile("cp.async.commit_group;");
    issue(1, 1); asm volatile("cp.async.commit_group;");
    issue(2, 2); asm volatile("cp.async.commit_group;");
    issue(3, 3); asm volatile("cp.async.commit_group;");

    const uint32_t aRow = warpM * 64 + (lane & 15);
    const uint32_t aKof = (lane >> 4) << 3;
    const uint32_t bRow = warpN * 64 + ((lane >> 4) << 3) + (lane & 7);
    const uint32_t bKof = ((lane >> 3) & 1) << 3;

    int scur = 0;           // kt % 5
    int snxt = 4;           // (kt+4) % 5
    for (int kt = 0; kt < 128; kt++) {
        asm volatile("cp.async.wait_group 3;");
        __syncthreads();

        const uint32_t sA = smb + (uint32_t)scur * STG_B;
        const uint32_t sB = sA + TILE_B;
#pragma unroll
        for (int ks = 0; ks < 2; ks++) {
            uint32_t a[4][4], b[8][2];
#pragma unroll
            for (int mt = 0; mt < 4; mt++) {
                uint32_t ad = sA + ((aRow + mt * 16) * HSTR + ks * 16 + aKof) * 2;
                asm volatile(
                    "ldmatrix.sync.aligned.m8n8.x4.shared.b16 {%0,%1,%2,%3}, [%4];"
                    : "=r"(a[mt][0]), "=r"(a[mt][1]), "=r"(a[mt][2]), "=r"(a[mt][3])
                    : "r"(ad));
            }
#pragma unroll
            for (int g = 0; g < 4; g++) {
                uint32_t bd = sB + ((bRow + g * 16) * HSTR + ks * 16 + bKof) * 2;
                asm volatile(
                    "ldmatrix.sync.aligned.m8n8.x4.shared.b16 {%0,%1,%2,%3}, [%4];"
                    : "=r"(b[2 * g][0]), "=r"(b[2 * g][1]),
                      "=r"(b[2 * g + 1][0]), "=r"(b[2 * g + 1][1])
                    : "r"(bd));
            }
#pragma unroll
            for (int mt = 0; mt < 4; mt++)
#pragma unroll
                for (int nt = 0; nt < 8; nt++) {
                    asm volatile(
                        "mma.sync.aligned.m16n8k16.row.col.f32.f16.f16.f32 "
                        "{%0,%1,%2,%3}, {%4,%5,%6,%7}, {%8,%9}, {%0,%1,%2,%3};\n"
                        : "+f"(acc[mt][nt][0]), "+f"(acc[mt][nt][1]),
                          "+f"(acc[mt][nt][2]), "+f"(acc[mt][nt][3])
                        : "r"(a[mt][0]), "r"(a[mt][1]), "r"(a[mt][2]), "r"(a[mt][3]),
                          "r"(b[nt][0]), "r"(b[nt][1]));
                }
        }

        if (kt + 4 < 128) issue(kt + 4, snxt);
        asm volatile("cp.async.commit_group;");

        scur = (scur == 4) ? 0 : scur + 1;
        snxt = (snxt == 4) ? 0 : snxt + 1;
    }

    // epilogue: un-scale, + bias, float2 stores
#pragma unroll
    for (int mt = 0; mt < 4; mt++) {
        const int r = bM + warpM * 64 + mt * 16 + gid;
#pragma unroll
        for (int nt = 0; nt < 8; nt++) {
            const int c = bN + warpN * 64 + nt * 8 + tig * 2;
            const float2 bz = *(const float2*)(bias + c);
            float2 v0, v1;
            v0.x = acc[mt][nt][0] * INV_SCALE + bz.x;
            v0.y = acc[mt][nt][1] * INV_SCALE + bz.y;
            v1.x = acc[mt][nt][2] * INV_SCALE + bz.x;
            v1.y = acc[mt][nt][3] * INV_SCALE + bz.y;
            *(float2*)(out + (size_t)r * 4096 + c) = v0;
            *(float2*)(out + (size_t)(r + 8) * 4096 + c) = v1;
        }
    }
}

// ---------------------------------------------------------------------------
extern "C" void kernel_launch(void* const* d_in, const int* in_sizes, int n_in,
                              void* d_out, int out_size) {
    const float* x      = (const float*)d_in[0];
    const float* first  = (const float*)d_in[1];
    const float* middle = (const float*)d_in[2];
    const float* last   = (const float*)d_in[3];
    const float* bias   = (const float*)d_in[4];
    float* out = (float*)d_out;

    mpo_prepA<<<8448, 256>>>(first, middle, x);   // stage1 (256) + convx (8192)
    mpo_stage2<<<1024, 256>>>(last);

    cudaFuncSetAttribute(mpo_gemm, cudaFuncAttributeMaxDynamicSharedMemorySize,
                         SMEM_BYTES);
    dim3 gg(32, 16);   // 32 n-tiles x 16 m-tiles
    mpo_gemm<<<gg, 128, SMEM_BYTES>>>(bias, out);
}

// round 16
// speedup vs baseline: 1.1170x; 1.1170x over previous
#include <cuda_runtime.h>
#include <cuda_fp16.h>
#include <cuda.h>
#include <cstdint>

// Function-pointer type for cuTensorMapEncodeTiled (cudaTypedefs.h on this
// toolchain doesn't expose the PFN_ alias; declare it ourselves from cuda.h types).
typedef CUresult (*TmaEncodeFn)(
    CUtensorMap*, CUtensorMapDataType, cuuint32_t, void*,
    const cuuint64_t*, const cuuint64_t*, const cuuint32_t*, const cuuint32_t*,
    CUtensorMapInterleave, CUtensorMapSwizzle, CUtensorMapL2promotion,
    CUtensorMapFloatOOBfill);

// ---------------------------------------------------------------------------
// Scratch (__device__ globals — no allocations allowed)
// ---------------------------------------------------------------------------
static __device__ float  g_T[16 * 16 * 16 * 16 * 16];   //  4 MB  T[i][j][m][n][s]
static __device__ __half g_Wh[4096 * 4096];             // 32 MB  Wh[n=mno][k=ijk], fp16 x1024
static __device__ __half g_Xh[2048 * 4096];             // 16 MB  X fp16

#define W_SCALE   1024.0f
#define INV_SCALE 0.0009765625f

// ---------------------------------------------------------------------------
// Prep A (merged, independent halves — proven, 12us):
//   blocks [0,256):    stage1  T[i,j,m,n,s] = sum_r first[i,r,m]*middle[j,r,s,n]
//   blocks [256,8448): convx   X float4 -> fp16
// ---------------------------------------------------------------------------
__global__ void mpo_prepA(const float* __restrict__ first,
                          const float* __restrict__ middle,
                          const float* __restrict__ x) {
    __shared__ float F[256];     // first[i][r][m]
    __shared__ float Md[4096];   // middle[j][r][s][n]
    const int t = threadIdx.x;
    if (blockIdx.x >= 256) {
        int id = (blockIdx.x - 256) * 256 + t;      // float4 index
        float4 v = ((const float4*)x)[id];
        __half2 lo = __floats2half2_rn(v.x, v.y);
        __half2 hi = __floats2half2_rn(v.z, v.w);
        uint2 p;
        p.x = *(uint32_t*)&lo;
        p.y = *(uint32_t*)&hi;
        ((uint2*)g_Xh)[id] = p;
        return;
    }
    const int i = blockIdx.x >> 4, j = blockIdx.x & 15;
    F[t] = first[i * 256 + t];
#pragma unroll
    for (int q = 0; q < 16; q++) Md[t + q * 256] = middle[j * 4096 + t + q * 256];
    __syncthreads();
#pragma unroll
    for (int q = 0; q < 16; q++) {
        int z = t + q * 256;                 // z = m*256 + n*16 + s
        int m = z >> 8, n = (z >> 4) & 15, s = z & 15;
        float acc = 0.f;
#pragma unroll
        for (int r = 0; r < 16; r++)
            acc += F[r * 16 + m] * Md[r * 256 + s * 16 + n];
        g_T[(i * 16 + j) * 4096 + z] = acc;
    }
}

// ---------------------------------------------------------------------------
// Stage 2 (o-split x4, proven): block b -> (m=b>>6, n=(b>>2)&15, og=b&3)
// ---------------------------------------------------------------------------
__global__ void mpo_stage2(const float* __restrict__ last) {
    __shared__ float L[4096];    // last[k][s][o]
    const int t = threadIdx.x;
    const int m = blockIdx.x >> 6, n = (blockIdx.x >> 2) & 15, og = blockIdx.x & 3;
#pragma unroll
    for (int q = 0; q < 16; q++) L[t + q * 256] = last[t + q * 256];
    float Ts[16];
    const float* tp = g_T + (size_t)t * 4096 + m * 256 + n * 16;
#pragma unroll
    for (int s = 0; s < 16; s++) Ts[s] = tp[s];
    __syncthreads();
#pragma unroll
    for (int oo = 0; oo < 4; oo++) {
        const int o = og * 4 + oo;
        __half v[16];
#pragma unroll
        for (int k = 0; k < 16; k++) {
            float acc = 0.f;
#pragma unroll
            for (int s = 0; s < 16; s++) acc += Ts[s] * L[k * 256 + s * 16 + o];
            v[k] = __float2half_rn(acc * W_SCALE);
        }
        __half* wp = g_Wh + (size_t)(m * 256 + n * 16 + o) * 4096 + t * 16;
        *(uint4*)(wp)     = *(const uint4*)(v);
        *(uint4*)(wp + 8) = *(const uint4*)(v + 8);
    }
}

// ---------------------------------------------------------------------------
// GEMM: out(2048x4096) = (Xh @ Wh^T) * 2^-10 + bias
// Proven math path (128 thr, 4 warps 64x64, BK=32, NSTAGE=4, issue at end),
// loads switched from per-thread cp.async to TMA (cp.async.bulk.tensor.2d,
// SWIZZLE_64B) + mbarrier ring. Tile: A/B 128 rows x 32 halves (64B rows).
// ---------------------------------------------------------------------------
#define TILE_B 8192                 // one operand tile: 128*64 B
#define STG_B  (2 * TILE_B)         // A + B per stage
#define NSTAGE 4
#define SMEM_BYTES (NSTAGE * STG_B) // 65536 B dynamic

__global__ void __launch_bounds__(128, 2)
mpo_gemm(const __grid_constant__ CUtensorMap tmA,
         const __grid_constant__ CUtensorMap tmB,
         const float* __restrict__ bias, float* __restrict__ out) {
    extern __shared__ __align__(1024) char sm[];
    __shared__ __align__(8) uint64_t mbar[NSTAGE];
    uint32_t smb, mb;
    asm("{ .reg .u64 t; cvta.to.shared.u64 t, %1; cvt.u32.u64 %0, t; }"
        : "=r"(smb) : "l"(sm));
    asm("{ .reg .u64 t; cvta.to.shared.u64 t, %1; cvt.u32.u64 %0, t; }"
        : "=r"(mb) : "l"(&mbar[0]));

    const int tid  = threadIdx.x;
    const int lane = tid & 31, wid = tid >> 5;
    const int gid  = lane >> 2, tig = lane & 3;
    const int warpM = wid & 1, warpN = wid >> 1;   // 2M x 2N warps
    const int bM = blockIdx.y << 7;
    const int bN = blockIdx.x << 7;

    if (tid == 0) {
#pragma unroll
        for (int s = 0; s < NSTAGE; s++)
            asm volatile("mbarrier.init.shared.b64 [%0], 1;"
                         :: "r"(mb + s * 8) : "memory");
    }
    __syncthreads();

    float acc[4][8][4];
#pragma unroll
    for (int mt = 0; mt < 4; mt++)
#pragma unroll
        for (int nt = 0; nt < 8; nt++)
#pragma unroll
            for (int q = 0; q < 4; q++) acc[mt][nt][q] = 0.f;

    // TMA issue for k-tile kt into stage s (thread 0 only)
    auto issue = [&](int kt, int s) {
        uint32_t bar = mb + s * 8;
        uint32_t dA = smb + (uint32_t)s * STG_B;
        uint32_t dB = dA + TILE_B;
        asm volatile("mbarrier.arrive.expect_tx.shared.b64 _, [%0], %1;"
                     :: "r"(bar), "r"((uint32_t)STG_B) : "memory");
        int cx = kt * 32;
        asm volatile(
            "cp.async.bulk.tensor.2d.shared::cta.global.tile.mbarrier::complete_tx::bytes "
            "[%0], [%1, {%2, %3}], [%4];"
            :: "r"(dA), "l"(&tmA), "r"(cx), "r"(bM), "r"(bar) : "memory");
        asm volatile(
            "cp.async.bulk.tensor.2d.shared::cta.global.tile.mbarrier::complete_tx::bytes "
            "[%0], [%1, {%2, %3}], [%4];"
            :: "r"(dB), "l"(&tmB), "r"(cx), "r"(bN), "r"(bar) : "memory");
    };

    if (tid == 0) {
        issue(0, 0);
        issue(1, 1);
        issue(2, 2);
    }

    // Precomputed swizzled fragment offsets (Swizzle<2,4,3> matches TMA SW64):
    // logical o = row*64 + colbytes (+ ks*32); physical = o ^ ((row&6)<<3)
    uint32_t aoff[4][2], boff[4][2];
    {
        const int cA = (lane >> 4) << 4;                 // 0 or 16 bytes
        const int rA = warpM * 64 + (lane & 15);
#pragma unroll
        for (int mt = 0; mt < 4; mt++) {
            int row = rA + mt * 16;
            uint32_t xo = (uint32_t)((row & 6) << 3);
            uint32_t o0 = (uint32_t)(row * 64 + cA);
            aoff[mt][0] = o0 ^ xo;
            aoff[mt][1] = (o0 + 32) ^ xo;
        }
        const int cB = ((lane >> 3) & 1) << 4;           // 0 or 16 bytes
        const int rB = warpN * 64 + ((lane >> 4) << 3) + (lane & 7);
#pragma unroll
        for (int g = 0; g < 4; g++) {
            int row = rB + g * 16;
            uint32_t xo = (uint32_t)((row & 6) << 3);
            uint32_t o0 = (uint32_t)(row * 64 + cB);
            boff[g][0] = o0 ^ xo;
            boff[g][1] = (o0 + 32) ^ xo;
        }
    }

    for (int kt = 0; kt < 128; kt++) {
        const int s = kt & 3;
        const uint32_t ph = (uint32_t)((kt >> 2) & 1);
        asm volatile(
            "{\n\t.reg .pred P;\n"
            "WL%=:\n\tmbarrier.try_wait.parity.shared.b64 P, [%0], %1;\n\t"
            "@P bra WD%=;\n\tbra WL%=;\nWD%=:\n\t}"
            :: "r"(mb + s * 8), "r"(ph) : "memory");
        __syncthreads();

        const uint32_t sA = smb + (uint32_t)s * STG_B;
        const uint32_t sB = sA + TILE_B;
#pragma unroll
        for (int ks = 0; ks < 2; ks++) {
            uint32_t a[4][4], b[8][2];
#pragma unroll
            for (int mt = 0; mt < 4; mt++) {
                asm volatile(
                    "ldmatrix.sync.aligned.m8n8.x4.shared.b16 {%0,%1,%2,%3}, [%4];"
                    : "=r"(a[mt][0]), "=r"(a[mt][1]), "=r"(a[mt][2]), "=r"(a[mt][3])
                    : "r"(sA + aoff[mt][ks]));
            }
#pragma unroll
            for (int g = 0; g < 4; g++) {
                asm volatile(
                    "ldmatrix.sync.aligned.m8n8.x4.shared.b16 {%0,%1,%2,%3}, [%4];"
                    : "=r"(b[2 * g][0]), "=r"(b[2 * g][1]),
                      "=r"(b[2 * g + 1][0]), "=r"(b[2 * g + 1][1])
                    : "r"(sB + boff[g][ks]));
            }
#pragma unroll
            for (int mt = 0; mt < 4; mt++)
#pragma unroll
                for (int nt = 0; nt < 8; nt++) {
                    asm volatile(
                        "mma.sync.aligned.m16n8k16.row.col.f32.f16.f16.f32 "
                        "{%0,%1,%2,%3}, {%4,%5,%6,%7}, {%8,%9}, {%0,%1,%2,%3};\n"
                        : "+f"(acc[mt][nt][0]), "+f"(acc[mt][nt][1]),
                          "+f"(acc[mt][nt][2]), "+f"(acc[mt][nt][3])
                        : "r"(a[mt][0]), "r"(a[mt][1]), "r"(a[mt][2]), "r"(a[mt][3]),
                          "r"(b[nt][0]), "r"(b[nt][1]));
                }
        }

        if (kt + 3 < 128 && tid == 0) issue(kt + 3, (kt + 3) & 3);
    }

    // epilogue: un-scale, + bias, float2 stores
#pragma unroll
    for (int mt = 0; mt < 4; mt++) {
        const int r = bM + warpM * 64 + mt * 16 + gid;
#pragma unroll
        for (int nt = 0; nt < 8; nt++) {
            const int c = bN + warpN * 64 + nt * 8 + tig * 2;
            const float2 bz = *(const float2*)(bias + c);
            float2 v0, v1;
            v0.x = acc[mt][nt][0] * INV_SCALE + bz.x;
            v0.y = acc[mt][nt][1] * INV_SCALE + bz.y;
            v1.x = acc[mt][nt][2] * INV_SCALE + bz.x;
            v1.y = acc[mt][nt][3] * INV_SCALE + bz.y;
            *(float2*)(out + (size_t)r * 4096 + c) = v0;
            *(float2*)(out + (size_t)(r + 8) * 4096 + c) = v1;
        }
    }
}

// ---------------------------------------------------------------------------
extern "C" void kernel_launch(void* const* d_in, const int* in_sizes, int n_in,
                              void* d_out, int out_size) {
    const float* x      = (const float*)d_in[0];
    const float* first  = (const float*)d_in[1];
    const float* middle = (const float*)d_in[2];
    const float* last   = (const float*)d_in[3];
    const float* bias   = (const float*)d_in[4];
    float* out = (float*)d_out;

    mpo_prepA<<<8448, 256>>>(first, middle, x);   // stage1 (256) + convx (8192)
    mpo_stage2<<<1024, 256>>>(last);

    // Build TMA descriptors (host-side pure computation; graph-capture safe —
    // descriptors are baked into the kernel node as by-value params).
    TmaEncodeFn enc = nullptr;
    {
        void* fp = nullptr;
        cudaDriverEntryPointQueryResult qr;
        if (cudaGetDriverEntryPointByVersion("cuTensorMapEncodeTiled", &fp, 12000,
                                             cudaEnableDefault, &qr) != cudaSuccess ||
            fp == nullptr) {
            cudaGetDriverEntryPoint("cuTensorMapEncodeTiled", &fp,
                                    cudaEnableDefault, &qr);
        }
        enc = (TmaEncodeFn)fp;
    }
    void *pX = nullptr, *pW = nullptr;
    cudaGetSymbolAddress(&pX, g_Xh);
    cudaGetSymbolAddress(&pW, g_Wh);

    CUtensorMap tmA, tmB;
    {
        cuuint64_t dims[2]  = {4096, 2048};
        cuuint64_t strd[1]  = {4096 * 2};
        cuuint32_t box[2]   = {32, 128};
        cuuint32_t es[2]    = {1, 1};
        enc(&tmA, CU_TENSOR_MAP_DATA_TYPE_FLOAT16, 2, pX, dims, strd, box, es,
            CU_TENSOR_MAP_INTERLEAVE_NONE, CU_TENSOR_MAP_SWIZZLE_64B,
            CU_TENSOR_MAP_L2_PROMOTION_L2_128B, CU_TENSOR_MAP_FLOAT_OOB_FILL_NONE);
    }
    {
        cuuint64_t dims[2]  = {4096, 4096};
        cuuint64_t strd[1]  = {4096 * 2};
        cuuint32_t box[2]   = {32, 128};
        cuuint32_t es[2]    = {1, 1};
        enc(&tmB, CU_TENSOR_MAP_DATA_TYPE_FLOAT16, 2, pW, dims, strd, box, es,
            CU_TENSOR_MAP_INTERLEAVE_NONE, CU_TENSOR_MAP_SWIZZLE_64B,
            CU_TENSOR_MAP_L2_PROMOTION_L2_128B, CU_TENSOR_MAP_FLOAT_OOB_FILL_NONE);
    }

    cudaFuncSetAttribute(mpo_gemm, cudaFuncAttributeMaxDynamicSharedMemorySize,
                         SMEM_BYTES);
    dim3 gg(32, 16);   // 32 n-tiles x 16 m-tiles
    mpo_gemm<<<gg, 128, SMEM_BYTES>>>(tmA, tmB, bias, out);
}